// round 10
// baseline (speedup 1.0000x reference)
#include <cuda_runtime.h>
#include <cuda_fp16.h>
#include <cuda_bf16.h>
#include <cstdint>

#define N_ATOMS 50000
#define N_PAIRS 800000
#define X_DIM 3
#define N_PROP 64
#define N_ROWS (N_ATOMS * X_DIM)   // 150000

// Scratch: Y = px@wi, Z = px@wj as fp16, each [150000 x 64] = 19.2 MB.
__device__ uint4 g_Yh[N_ROWS * 8];
__device__ uint4 g_Zh[N_ROWS * 8];

// ---- smem address + ldmatrix + mma helpers -------------------------------
__device__ __forceinline__ uint32_t smem_u32(const void* p) {
    return (uint32_t)__cvta_generic_to_shared(p);
}
__device__ __forceinline__ void ldsm_x4(uint32_t& r0, uint32_t& r1,
                                        uint32_t& r2, uint32_t& r3, uint32_t a) {
    asm volatile("ldmatrix.sync.aligned.m8n8.x4.shared.b16 {%0,%1,%2,%3}, [%4];"
                 : "=r"(r0), "=r"(r1), "=r"(r2), "=r"(r3) : "r"(a));
}
__device__ __forceinline__ void ldsm_x4_t(uint32_t& r0, uint32_t& r1,
                                          uint32_t& r2, uint32_t& r3, uint32_t a) {
    asm volatile("ldmatrix.sync.aligned.m8n8.x4.trans.shared.b16 {%0,%1,%2,%3}, [%4];"
                 : "=r"(r0), "=r"(r1), "=r"(r2), "=r"(r3) : "r"(a));
}
__device__ __forceinline__ void mma_16816(float& d0, float& d1, float& d2, float& d3,
                                          uint32_t a0, uint32_t a1, uint32_t a2, uint32_t a3,
                                          uint32_t b0, uint32_t b1) {
    asm volatile("mma.sync.aligned.m16n8k16.row.col.f32.f16.f16.f32 "
                 "{%0,%1,%2,%3}, {%4,%5,%6,%7}, {%8,%9}, {%0,%1,%2,%3};"
                 : "+f"(d0), "+f"(d1), "+f"(d2), "+f"(d3)
                 : "r"(a0), "r"(a1), "r"(a2), "r"(a3), "r"(b0), "r"(b1));
}

// ---------------------------------------------------------------------------
// Kernel 1: C[150000 x 128] = px[150000 x 64] @ [wi | wj] via HMMA.
// Block: 256 thr (8 warps), tile M=128 N=128 K=64 (one shot, no k gmem loop).
// Warp grid 2(M) x 4(N): each warp 64x32 via 4x4 m16n8k16 tiles, k in 4 steps.
// A/B staged in smem fp16 with 16B-chunk XOR swizzle for conflict-free LDSM.
// ---------------------------------------------------------------------------
__global__ void __launch_bounds__(256) precompute_mma(
    const float* __restrict__ px,
    const float* __restrict__ wi,
    const float* __restrict__ wj)
{
    __shared__ __half sA[128 * 64];   // rows of 128B, swizzled
    __shared__ __half sB[64 * 128];   // rows of 256B, swizzled

    const int tid  = threadIdx.x;
    const int row0 = blockIdx.x * 128;

    // Fill sA: px rows [row0, row0+128), f32 -> fp16, zero-fill OOB rows.
#pragma unroll
    for (int l = 0; l < 8; l++) {
        int idx = tid + l * 256;            // 0..2047 float4s
        int r   = idx >> 4;                 // 16 float4 per row
        int c4  = idx & 15;
        int row = row0 + r;
        float4 v = make_float4(0.f, 0.f, 0.f, 0.f);
        if (row < N_ROWS) v = __ldg((const float4*)px + row * 16 + c4);
        __half2 h0 = __floats2half2_rn(v.x, v.y);
        __half2 h1 = __floats2half2_rn(v.z, v.w);
        int chunk = c4 >> 1;                // 16B chunk 0..7
        int sw = r * 128 + ((chunk ^ (r & 7)) << 4) + ((c4 & 1) << 3);
        *(uint2*)((char*)sA + sw) =
            make_uint2(*(unsigned*)&h0, *(unsigned*)&h1);
    }
    // Fill sB: [64 z][128 g], cols 0-63 = wi, 64-127 = wj.
#pragma unroll
    for (int l = 0; l < 8; l++) {
        int idx = tid + l * 256;            // 0..2047 float4s
        int z   = idx >> 5;                 // 32 float4 per row
        int c4  = idx & 31;
        int g   = c4 * 4;
        const float* src = (g < 64) ? (wi + z * 64 + g) : (wj + z * 64 + g - 64);
        float4 v = __ldg((const float4*)src);
        __half2 h0 = __floats2half2_rn(v.x, v.y);
        __half2 h1 = __floats2half2_rn(v.z, v.w);
        int chunk = c4 >> 1;                // 0..15 (XOR touches low 3 bits)
        int sw = z * 256 + ((chunk ^ (z & 7)) << 4) + ((c4 & 1) << 3);
        *(uint2*)((char*)sB + sw) =
            make_uint2(*(unsigned*)&h0, *(unsigned*)&h1);
    }
    __syncthreads();

    const int lane   = tid & 31;
    const int wid    = tid >> 5;
    const int warp_m = wid & 1;             // 2 warp rows  (64 M each)
    const int warp_n = wid >> 1;            // 4 warp cols  (32 N each)
    const int mi     = lane >> 3;           // ldmatrix matrix index
    const int lr     = lane & 7;            // ldmatrix row-in-matrix

    const uint32_t sA_base = smem_u32(sA);
    const uint32_t sB_base = smem_u32(sB);

    float acc[4][4][4];
#pragma unroll
    for (int mt = 0; mt < 4; mt++)
#pragma unroll
        for (int nt = 0; nt < 4; nt++)
#pragma unroll
            for (int e = 0; e < 4; e++) acc[mt][nt][e] = 0.f;

#pragma unroll
    for (int ks = 0; ks < 4; ks++) {
        // B fragments: 2 x ldmatrix.x4.trans cover 4 n-tiles of 8.
        uint32_t b[2][4];
#pragma unroll
        for (int ntp = 0; ntp < 2; ntp++) {
            int n0  = warp_n * 32 + ntp * 16;
            int k   = ks * 16 + (mi & 1) * 8 + lr;       // smem B row
            int col = n0 + (mi >> 1) * 8;
            uint32_t a = sB_base + k * 256 + (((col >> 3) ^ (k & 7)) << 4);
            ldsm_x4_t(b[ntp][0], b[ntp][1], b[ntp][2], b[ntp][3], a);
        }
        // A fragments per m-tile, then 4 mma each.
#pragma unroll
        for (int mt = 0; mt < 4; mt++) {
            int row  = warp_m * 64 + mt * 16 + (mi & 1) * 8 + lr;
            int colh = ks * 16 + (mi >> 1) * 8;
            uint32_t a = sA_base + row * 128 + (((colh >> 3) ^ (row & 7)) << 4);
            uint32_t A0, A1, A2, A3;
            ldsm_x4(A0, A1, A2, A3, a);
#pragma unroll
            for (int nt = 0; nt < 4; nt++) {
                int ntp = nt >> 1, pr = (nt & 1) * 2;
                mma_16816(acc[mt][nt][0], acc[mt][nt][1],
                          acc[mt][nt][2], acc[mt][nt][3],
                          A0, A1, A2, A3, b[ntp][pr], b[ntp][pr + 1]);
            }
        }
    }

    // Epilogue: accum (m16n8 layout) -> fp16 -> g_Yh / g_Zh.
    // warp_n 0,1 -> cols 0..63 (Y); warp_n 2,3 -> cols 64..127 (Z).
    const int quad = lane >> 2;
    const int tq   = lane & 3;
    unsigned* dstb = (warp_n < 2) ? (unsigned*)g_Yh : (unsigned*)g_Zh;
    const int gcb  = (warp_n < 2) ? warp_n * 32 : (warp_n - 2) * 32;
#pragma unroll
    for (int mt = 0; mt < 4; mt++) {
#pragma unroll
        for (int nt = 0; nt < 4; nt++) {
            int grow = row0 + warp_m * 64 + mt * 16 + quad;
            int gc   = gcb + nt * 8 + tq * 2;
            __half2 lo = __floats2half2_rn(acc[mt][nt][0], acc[mt][nt][1]);
            __half2 hi = __floats2half2_rn(acc[mt][nt][2], acc[mt][nt][3]);
            if (grow < N_ROWS)
                dstb[grow * 32 + (gc >> 1)] = *(unsigned*)&lo;
            if (grow + 8 < N_ROWS)
                dstb[(grow + 8) * 32 + (gc >> 1)] = *(unsigned*)&hi;
        }
    }
}

// ---------------------------------------------------------------------------
// Kernel 2: out[p] = Y[i_p] + Z[j_p].
// Block = 384 thr = 16 pair-slots x 24 lanes; each thread does 4 pairs
// (slots stride 16) -> 64 pairs/block. Lane loads one uint4 (8 halves) per
// side per pair: LDG.128, half the load-instruction count of the uint2
// version, MLP=8. Stores: two adjacent float4 per lane (sector-dense).
// ---------------------------------------------------------------------------
__global__ void __launch_bounds__(384) gather_add_kernel(
    const int2* __restrict__ ind,
    float4* __restrict__ out)
{
    __shared__ int2 s_ij[64];

    const int tid  = threadIdx.x;
    const int base = blockIdx.x * 64;

    if (tid < 64) s_ij[tid] = __ldg(&ind[base + tid]);
    __syncthreads();

    const int lp = tid / 24;               // pair slot 0..15
    const int t  = tid - lp * 24;          // lane 0..23 (uint4 = 8 halves)

    const uint4* Y = g_Yh;                 // 24 uint4 per atom (3x64 fp16)
    const uint4* Z = g_Zh;

    // Issue all 8 independent LDG.128 gathers first (MLP=8).
    uint4 ya[4], zb[4];
#pragma unroll
    for (int k = 0; k < 4; k++) {
        int2 ij = s_ij[lp + 16 * k];
        ya[k] = __ldg(&Y[ij.x * 24 + t]);
        zb[k] = __ldg(&Z[ij.y * 24 + t]);
    }

#pragma unroll
    for (int k = 0; k < 4; k++) {
        float2 y0 = __half22float2(*(const __half2*)&ya[k].x);
        float2 y1 = __half22float2(*(const __half2*)&ya[k].y);
        float2 y2 = __half22float2(*(const __half2*)&ya[k].z);
        float2 y3 = __half22float2(*(const __half2*)&ya[k].w);
        float2 z0 = __half22float2(*(const __half2*)&zb[k].x);
        float2 z1 = __half22float2(*(const __half2*)&zb[k].y);
        float2 z2 = __half22float2(*(const __half2*)&zb[k].z);
        float2 z3 = __half22float2(*(const __half2*)&zb[k].w);
        float4 r0 = { y0.x + z0.x, y0.y + z0.y, y1.x + z1.x, y1.y + z1.y };
        float4 r1 = { y2.x + z2.x, y2.y + z2.y, y3.x + z3.x, y3.y + z3.y };
        const int p = base + lp + 16 * k;
        __stcs(&out[p * 48 + 2 * t],     r0);
        __stcs(&out[p * 48 + 2 * t + 1], r1);
    }
}

// ---------------------------------------------------------------------------
extern "C" void kernel_launch(void* const* d_in, const int* in_sizes, int n_in,
                              void* d_out, int out_size)
{
    const int2*  ind = (const int2*) d_in[0];   // [800000, 2] int32
    const float* px  = (const float*)d_in[1];   // [50000, 3, 64]
    const float* wi  = (const float*)d_in[2];   // [64, 64]
    const float* wj  = (const float*)d_in[3];   // [64, 64]
    float4*      out = (float4*)d_out;          // [800000, 3, 64] f32

    (void)in_sizes; (void)n_in; (void)out_size;

    precompute_mma<<<(N_ROWS + 127) / 128, 256>>>(px, wi, wj);
    gather_add_kernel<<<N_PAIRS / 64, 384>>>(ind, out);
}

// round 11
// speedup vs baseline: 1.3864x; 1.3864x over previous
#include <cuda_runtime.h>
#include <cuda_fp16.h>
#include <cuda_bf16.h>
#include <cstdint>

#define N_ATOMS 50000
#define N_PAIRS 800000
#define X_DIM 3
#define N_PROP 64
#define N_ROWS (N_ATOMS * X_DIM)   // 150000

// Scratch: Y = px@wi, Z = px@wj as fp16, stored PER ATOM (192 halves = 24
// uint4), permuted so gather lane t's uint4 holds output floats
// [4t..4t+3] and [96+4t..96+4t+3]. 50000 * 24 uint4 = 19.2 MB each.
__device__ uint4 g_Yh[N_ATOMS * 24];
__device__ uint4 g_Zh[N_ATOMS * 24];

// ---- smem address + ldmatrix + mma helpers -------------------------------
__device__ __forceinline__ uint32_t smem_u32(const void* p) {
    return (uint32_t)__cvta_generic_to_shared(p);
}
__device__ __forceinline__ void ldsm_x4(uint32_t& r0, uint32_t& r1,
                                        uint32_t& r2, uint32_t& r3, uint32_t a) {
    asm volatile("ldmatrix.sync.aligned.m8n8.x4.shared.b16 {%0,%1,%2,%3}, [%4];"
                 : "=r"(r0), "=r"(r1), "=r"(r2), "=r"(r3) : "r"(a));
}
__device__ __forceinline__ void ldsm_x4_t(uint32_t& r0, uint32_t& r1,
                                          uint32_t& r2, uint32_t& r3, uint32_t a) {
    asm volatile("ldmatrix.sync.aligned.m8n8.x4.trans.shared.b16 {%0,%1,%2,%3}, [%4];"
                 : "=r"(r0), "=r"(r1), "=r"(r2), "=r"(r3) : "r"(a));
}
__device__ __forceinline__ void mma_16816(float& d0, float& d1, float& d2, float& d3,
                                          uint32_t a0, uint32_t a1, uint32_t a2, uint32_t a3,
                                          uint32_t b0, uint32_t b1) {
    asm volatile("mma.sync.aligned.m16n8k16.row.col.f32.f16.f16.f32 "
                 "{%0,%1,%2,%3}, {%4,%5,%6,%7}, {%8,%9}, {%0,%1,%2,%3};"
                 : "+f"(d0), "+f"(d1), "+f"(d2), "+f"(d3)
                 : "r"(a0), "r"(a1), "r"(a2), "r"(a3), "r"(b0), "r"(b1));
}

// Permuted half2 store into the per-atom gather-friendly layout.
// dstb: base in half2 units. grow = row in [0,150000), gc = even col in [0,64).
__device__ __forceinline__ void store_perm(unsigned* dstb, int grow, int gc,
                                           __half2 v) {
    if (grow >= N_ROWS) return;
    int atom = grow / 3;
    int x    = grow - atom * 3;
    int f    = x * 64 + gc;                 // even flat index in [0,192)
    int pidx;
    if (f < 96) pidx = ((f >> 2) << 3) + (f & 3);
    else {
        int ff = f - 96;
        pidx = ((ff >> 2) << 3) + 4 + (ff & 3);
    }
    dstb[atom * 96 + (pidx >> 1)] = *(unsigned*)&v;
}

// ---------------------------------------------------------------------------
// Kernel 1: C[150000 x 128] = px[150000 x 64] @ [wi | wj] via HMMA.
// Block: 256 thr (8 warps), tile M=128 N=128 K=64 one shot.
// Warp grid 2(M) x 4(N): each warp 64x32 via 4x4 m16n8k16 tiles.
// ---------------------------------------------------------------------------
__global__ void __launch_bounds__(256) precompute_mma(
    const float* __restrict__ px,
    const float* __restrict__ wi,
    const float* __restrict__ wj)
{
    __shared__ __half sA[128 * 64];   // rows of 128B, swizzled
    __shared__ __half sB[64 * 128];   // rows of 256B, swizzled

    const int tid  = threadIdx.x;
    const int row0 = blockIdx.x * 128;

    // Fill sA: px rows [row0, row0+128), f32 -> fp16, zero-fill OOB rows.
#pragma unroll
    for (int l = 0; l < 8; l++) {
        int idx = tid + l * 256;            // 0..2047 float4s
        int r   = idx >> 4;                 // 16 float4 per row
        int c4  = idx & 15;
        int row = row0 + r;
        float4 v = make_float4(0.f, 0.f, 0.f, 0.f);
        if (row < N_ROWS) v = __ldg((const float4*)px + row * 16 + c4);
        __half2 h0 = __floats2half2_rn(v.x, v.y);
        __half2 h1 = __floats2half2_rn(v.z, v.w);
        int chunk = c4 >> 1;                // 16B chunk 0..7
        int sw = r * 128 + ((chunk ^ (r & 7)) << 4) + ((c4 & 1) << 3);
        *(uint2*)((char*)sA + sw) =
            make_uint2(*(unsigned*)&h0, *(unsigned*)&h1);
    }
    // Fill sB: [64 z][128 g], cols 0-63 = wi, 64-127 = wj.
#pragma unroll
    for (int l = 0; l < 8; l++) {
        int idx = tid + l * 256;            // 0..2047 float4s
        int z   = idx >> 5;                 // 32 float4 per row
        int c4  = idx & 31;
        int g   = c4 * 4;
        const float* src = (g < 64) ? (wi + z * 64 + g) : (wj + z * 64 + g - 64);
        float4 v = __ldg((const float4*)src);
        __half2 h0 = __floats2half2_rn(v.x, v.y);
        __half2 h1 = __floats2half2_rn(v.z, v.w);
        int chunk = c4 >> 1;
        int sw = z * 256 + ((chunk ^ (z & 7)) << 4) + ((c4 & 1) << 3);
        *(uint2*)((char*)sB + sw) =
            make_uint2(*(unsigned*)&h0, *(unsigned*)&h1);
    }
    __syncthreads();

    const int lane   = tid & 31;
    const int wid    = tid >> 5;
    const int warp_m = wid & 1;             // 2 warp rows  (64 M each)
    const int warp_n = wid >> 1;            // 4 warp cols  (32 N each)
    const int mi     = lane >> 3;
    const int lr     = lane & 7;

    const uint32_t sA_base = smem_u32(sA);
    const uint32_t sB_base = smem_u32(sB);

    float acc[4][4][4];
#pragma unroll
    for (int mt = 0; mt < 4; mt++)
#pragma unroll
        for (int nt = 0; nt < 4; nt++)
#pragma unroll
            for (int e = 0; e < 4; e++) acc[mt][nt][e] = 0.f;

#pragma unroll
    for (int ks = 0; ks < 4; ks++) {
        uint32_t b[2][4];
#pragma unroll
        for (int ntp = 0; ntp < 2; ntp++) {
            int n0  = warp_n * 32 + ntp * 16;
            int k   = ks * 16 + (mi & 1) * 8 + lr;
            int col = n0 + (mi >> 1) * 8;
            uint32_t a = sB_base + k * 256 + (((col >> 3) ^ (k & 7)) << 4);
            ldsm_x4_t(b[ntp][0], b[ntp][1], b[ntp][2], b[ntp][3], a);
        }
#pragma unroll
        for (int mt = 0; mt < 4; mt++) {
            int row  = warp_m * 64 + mt * 16 + (mi & 1) * 8 + lr;
            int colh = ks * 16 + (mi >> 1) * 8;
            uint32_t a = sA_base + row * 128 + (((colh >> 3) ^ (row & 7)) << 4);
            uint32_t A0, A1, A2, A3;
            ldsm_x4(A0, A1, A2, A3, a);
#pragma unroll
            for (int nt = 0; nt < 4; nt++) {
                int ntp = nt >> 1, pr = (nt & 1) * 2;
                mma_16816(acc[mt][nt][0], acc[mt][nt][1],
                          acc[mt][nt][2], acc[mt][nt][3],
                          A0, A1, A2, A3, b[ntp][pr], b[ntp][pr + 1]);
            }
        }
    }

    // Epilogue: accum -> fp16 -> permuted per-atom layout in g_Yh / g_Zh.
    const int quad = lane >> 2;
    const int tq   = lane & 3;
    unsigned* dstb = (warp_n < 2) ? (unsigned*)g_Yh : (unsigned*)g_Zh;
    const int gcb  = (warp_n < 2) ? warp_n * 32 : (warp_n - 2) * 32;
#pragma unroll
    for (int mt = 0; mt < 4; mt++) {
#pragma unroll
        for (int nt = 0; nt < 4; nt++) {
            int grow = row0 + warp_m * 64 + mt * 16 + quad;
            int gc   = gcb + nt * 8 + tq * 2;
            __half2 lo = __floats2half2_rn(acc[mt][nt][0], acc[mt][nt][1]);
            __half2 hi = __floats2half2_rn(acc[mt][nt][2], acc[mt][nt][3]);
            store_perm(dstb, grow,     gc, lo);
            store_perm(dstb, grow + 8, gc, hi);
        }
    }
}

// ---------------------------------------------------------------------------
// Kernel 2: out[p] = Y[i_p] + Z[j_p].
// Block = 384 thr = 16 pair-slots x 24 lanes; each thread does 4 pairs
// (slots stride 16) -> 64 pairs/block. Lane t loads one uint4 (8 permuted
// halves) per side per pair (LDG.128, per-pair-contiguous), MLP=8.
// Permutation makes BOTH stores dense: float4 at p*48+t and p*48+24+t.
// ---------------------------------------------------------------------------
__global__ void __launch_bounds__(384) gather_add_kernel(
    const int2* __restrict__ ind,
    float4* __restrict__ out)
{
    __shared__ int2 s_ij[64];

    const int tid  = threadIdx.x;
    const int base = blockIdx.x * 64;

    if (tid < 64) s_ij[tid] = __ldg(&ind[base + tid]);
    __syncthreads();

    const int lp = tid / 24;               // pair slot 0..15
    const int t  = tid - lp * 24;          // lane 0..23

    const uint4* Y = g_Yh;                 // 24 uint4 per atom
    const uint4* Z = g_Zh;

    // Issue all 8 independent LDG.128 gathers first (MLP=8).
    uint4 ya[4], zb[4];
#pragma unroll
    for (int k = 0; k < 4; k++) {
        int2 ij = s_ij[lp + 16 * k];
        ya[k] = __ldg(&Y[ij.x * 24 + t]);
        zb[k] = __ldg(&Z[ij.y * 24 + t]);
    }

#pragma unroll
    for (int k = 0; k < 4; k++) {
        float2 y0 = __half22float2(*(const __half2*)&ya[k].x);
        float2 y1 = __half22float2(*(const __half2*)&ya[k].y);
        float2 y2 = __half22float2(*(const __half2*)&ya[k].z);
        float2 y3 = __half22float2(*(const __half2*)&ya[k].w);
        float2 z0 = __half22float2(*(const __half2*)&zb[k].x);
        float2 z1 = __half22float2(*(const __half2*)&zb[k].y);
        float2 z2 = __half22float2(*(const __half2*)&zb[k].z);
        float2 z3 = __half22float2(*(const __half2*)&zb[k].w);
        // halves 0-3 -> out floats [4t..4t+3]; halves 4-7 -> [96+4t..96+4t+3]
        float4 r0 = { y0.x + z0.x, y0.y + z0.y, y1.x + z1.x, y1.y + z1.y };
        float4 r1 = { y2.x + z2.x, y2.y + z2.y, y3.x + z3.x, y3.y + z3.y };
        const int p = base + lp + 16 * k;
        __stcs(&out[p * 48 + t],      r0);
        __stcs(&out[p * 48 + 24 + t], r1);
    }
}

// ---------------------------------------------------------------------------
extern "C" void kernel_launch(void* const* d_in, const int* in_sizes, int n_in,
                              void* d_out, int out_size)
{
    const int2*  ind = (const int2*) d_in[0];   // [800000, 2] int32
    const float* px  = (const float*)d_in[1];   // [50000, 3, 64]
    const float* wi  = (const float*)d_in[2];   // [64, 64]
    const float* wj  = (const float*)d_in[3];   // [64, 64]
    float4*      out = (float4*)d_out;          // [800000, 3, 64] f32

    (void)in_sizes; (void)n_in; (void)out_size;

    precompute_mma<<<(N_ROWS + 127) / 128, 256>>>(px, wi, wj);
    gather_add_kernel<<<N_PAIRS / 64, 384>>>(ind, out);
}